// round 2
// baseline (speedup 1.0000x reference)
#include <cuda_runtime.h>
#include <math.h>

// Problem constants (fixed by the reference)
#define TT 8192          // tokens = B*L
#define DD 1024          // input dim
#define HH 1024          // expert hidden
#define EE 8             // experts
#define KSEL 2           // top-k
#define SLOTS (TT*KSEL)  // 16384 token-expert pairs

// ---------------- device scratch (no allocations allowed) ----------------
__device__ int   g_top_idx[SLOTS];
__device__ float g_top_gate[SLOTS];
__device__ float g_probs[TT*EE];
__device__ float g_lse2[TT];
__device__ float g_probs_sum[EE];
__device__ float g_gates_sum[EE];
__device__ int   g_count[EE];
__device__ int   g_off[EE+1];
__device__ int   g_cur[EE];
__device__ int   g_slot_tok[SLOTS];
__device__ float g_slot_gate[SLOTS];
__device__ float g_h[(size_t)SLOTS * HH];   // 64 MB intermediate (GELU(x@w_in))
__device__ float g_z;                        // sum of lse^2

// ---------------- helpers ----------------
__device__ __forceinline__ float gelu_tanh(float v) {
    // jax.nn.gelu default (approximate=True)
    const float c0 = 0.7978845608028654f;    // sqrt(2/pi)
    return 0.5f * v * (1.0f + tanhf(c0 * (v + 0.044715f * v * v * v)));
}

// ---------------- 0) reset accumulators (graph-replay safe) ----------------
__global__ void init_kernel() {
    int i = threadIdx.x;
    if (i < EE) { g_probs_sum[i] = 0.f; g_gates_sum[i] = 0.f; g_count[i] = 0; g_cur[i] = 0; }
    if (i == 0) g_z = 0.f;
}

// ---------------- 1) gating: logits, softmax, top-2, lse^2 ----------------
__global__ void __launch_bounds__(128) gate_kernel(const float* __restrict__ x,
                                                   const float* __restrict__ wg) {
    int t = blockIdx.x;
    int tid = threadIdx.x;   // 128 threads
    const float* xr = x + (size_t)t * DD;
    float part[EE];
#pragma unroll
    for (int e = 0; e < EE; e++) part[e] = 0.f;

    for (int i = tid; i < DD; i += 128) {
        float xv = xr[i];
        const float4* w4 = (const float4*)(wg + (size_t)i * EE);
        float4 w0 = w4[0], w1 = w4[1];
        part[0] += xv * w0.x; part[1] += xv * w0.y;
        part[2] += xv * w0.z; part[3] += xv * w0.w;
        part[4] += xv * w1.x; part[5] += xv * w1.y;
        part[6] += xv * w1.z; part[7] += xv * w1.w;
    }
    // warp reduce
#pragma unroll
    for (int e = 0; e < EE; e++)
#pragma unroll
        for (int o = 16; o > 0; o >>= 1)
            part[e] += __shfl_down_sync(0xffffffffu, part[e], o);

    __shared__ float sred[4][EE];
    int wid = tid >> 5, lid = tid & 31;
    if (lid == 0)
#pragma unroll
        for (int e = 0; e < EE; e++) sred[wid][e] = part[e];
    __syncthreads();

    if (tid == 0) {
        float logit[EE];
#pragma unroll
        for (int e = 0; e < EE; e++)
            logit[e] = sred[0][e] + sred[1][e] + sred[2][e] + sred[3][e];
        float mx = logit[0];
#pragma unroll
        for (int e = 1; e < EE; e++) mx = fmaxf(mx, logit[e]);
        float p[EE]; float se = 0.f;
#pragma unroll
        for (int e = 0; e < EE; e++) { p[e] = expf(logit[e] - mx); se += p[e]; }
        float inv = 1.f / se;
#pragma unroll
        for (int e = 0; e < EE; e++) { p[e] *= inv; g_probs[(size_t)t * EE + e] = p[e]; }
        float lse = mx + logf(se);
        g_lse2[t] = lse * lse;

        // top-2 (jax top_k: largest first, lowest index on tie)
        int i0 = 0;
#pragma unroll
        for (int e = 1; e < EE; e++) if (p[e] > p[i0]) i0 = e;
        int i1 = -1;
#pragma unroll
        for (int e = 0; e < EE; e++) {
            if (e == i0) continue;
            if (i1 < 0 || p[e] > p[i1]) i1 = e;
        }
        g_top_idx[t*2+0] = i0; g_top_gate[t*2+0] = p[i0];
        g_top_idx[t*2+1] = i1; g_top_gate[t*2+1] = p[i1];
    }
}

// ---------------- 2) reduce per-expert stats ----------------
__global__ void __launch_bounds__(256) reduce_kernel() {
    __shared__ float sp[EE]; __shared__ float sg[EE]; __shared__ int sc[EE]; __shared__ float sz;
    int tid = threadIdx.x;
    if (tid < EE) { sp[tid] = 0.f; sg[tid] = 0.f; sc[tid] = 0; }
    if (tid == 0) sz = 0.f;
    __syncthreads();

    int t = blockIdx.x * blockDim.x + tid;
    float p[EE]; float z = 0.f;
    if (t < TT) {
#pragma unroll
        for (int e = 0; e < EE; e++) p[e] = g_probs[(size_t)t * EE + e];
        z = g_lse2[t];
    } else {
#pragma unroll
        for (int e = 0; e < EE; e++) p[e] = 0.f;
    }
#pragma unroll
    for (int e = 0; e < EE; e++)
#pragma unroll
        for (int o = 16; o > 0; o >>= 1)
            p[e] += __shfl_down_sync(0xffffffffu, p[e], o);
#pragma unroll
    for (int o = 16; o > 0; o >>= 1) z += __shfl_down_sync(0xffffffffu, z, o);

    if ((tid & 31) == 0) {
#pragma unroll
        for (int e = 0; e < EE; e++) atomicAdd(&sp[e], p[e]);
        atomicAdd(&sz, z);
    }
    if (t < TT) {
#pragma unroll
        for (int k = 0; k < KSEL; k++) {
            int e = g_top_idx[t*2+k];
            atomicAdd(&sg[e], g_top_gate[t*2+k]);
            atomicAdd(&sc[e], 1);
        }
    }
    __syncthreads();
    if (tid < EE) {
        atomicAdd(&g_probs_sum[tid], sp[tid]);
        atomicAdd(&g_gates_sum[tid], sg[tid]);
        atomicAdd(&g_count[tid], sc[tid]);
    }
    if (tid == 0) atomicAdd(&g_z, sz);
}

// ---------------- 3) prefix + scatter ----------------
__global__ void prefix_kernel() {
    if (threadIdx.x == 0) {
        int s = 0;
#pragma unroll
        for (int e = 0; e < EE; e++) { g_off[e] = s; s += g_count[e]; }
        g_off[EE] = s;
    }
}

__global__ void __launch_bounds__(256) scatter_kernel() {
    int t = blockIdx.x * blockDim.x + threadIdx.x;
    if (t >= TT) return;
#pragma unroll
    for (int k = 0; k < KSEL; k++) {
        int e = g_top_idx[t*2+k];
        int pos = g_off[e] + atomicAdd(&g_cur[e], 1);
        g_slot_tok[pos] = t;
        g_slot_gate[pos] = g_top_gate[t*2+k];
    }
}

// ---------------- 4/5) grouped GEMM (double-buffered SGEMM) ----------------
// MODE 0: h = gelu(x[tok] @ w_in[e])           -> g_h
// MODE 1: y[tok] += gate * (g_h @ w_out[e])    (atomicAdd combine)
// Tile: 128(M) x 128(N) x 8(K), 256 threads, 8x8 per thread, double-buffered SMEM.
template<int MODE>
__global__ void __launch_bounds__(256) gemm_kernel(const float* __restrict__ x,
                                                   const float* __restrict__ B_all,
                                                   float* __restrict__ y) {
    int e = blockIdx.z;
    int cnt = g_count[e];
    int m0 = blockIdx.x * 128;
    if (m0 >= cnt) return;
    int n0 = blockIdx.y * 128;
    int base = g_off[e];
    const float* B = B_all + (size_t)e * DD * HH;

    __shared__ float As[2][8][128];
    __shared__ float Bs[2][8][128];

    int tid = threadIdx.x;
    int tx = tid & 15, ty = tid >> 4;      // 16x16 thread grid, 8x8 microtile

    float acc[8][8];
#pragma unroll
    for (int i = 0; i < 8; i++)
#pragma unroll
        for (int j = 0; j < 8; j++) acc[i][j] = 0.f;

    // A-load: 256 float4 per K-tile (128 rows x 8 k), one per thread
    int rA  = tid >> 1;            // row 0..127
    int kqA = (tid & 1) * 4;       // k offset 0 or 4
    int mA = m0 + rA;
    bool vA = (mA < cnt);
    int slotA = vA ? (base + mA) : base;
    const float* aptr;
    if (MODE == 0) {
        int tok = vA ? g_slot_tok[slotA] : 0;
        aptr = x + (size_t)tok * DD + kqA;
    } else {
        aptr = g_h + (size_t)slotA * HH + kqA;
    }
    // B-load: 256 float4 per K-tile (8 k x 128 n), one per thread
    int kB = tid >> 5;             // 0..7
    int nB = (tid & 31) * 4;       // float4 col offset
    const float* bptr = B + (size_t)kB * 1024 + n0 + nB;

    // prologue: load tile 0
    float4 av = vA ? *(const float4*)(aptr) : make_float4(0.f,0.f,0.f,0.f);
    float4 bv = *(const float4*)(bptr);

    int buf = 0;
    As[0][kqA+0][rA] = av.x; As[0][kqA+1][rA] = av.y;
    As[0][kqA+2][rA] = av.z; As[0][kqA+3][rA] = av.w;
    *(float4*)&Bs[0][kB][nB] = bv;
    __syncthreads();

    for (int k0 = 0; k0 < DD; k0 += 8) {
        int nxt = k0 + 8;
        if (nxt < DD) {
            av = vA ? *(const float4*)(aptr + nxt) : make_float4(0.f,0.f,0.f,0.f);
            bv = *(const float4*)(bptr + (size_t)nxt * 1024);
        }
#pragma unroll
        for (int kk = 0; kk < 8; kk++) {
            float4 a0 = *(const float4*)&As[buf][kk][ty * 8];
            float4 a1 = *(const float4*)&As[buf][kk][ty * 8 + 4];
            float4 b0 = *(const float4*)&Bs[buf][kk][tx * 8];
            float4 b1 = *(const float4*)&Bs[buf][kk][tx * 8 + 4];
            float ar[8] = {a0.x,a0.y,a0.z,a0.w,a1.x,a1.y,a1.z,a1.w};
            float br[8] = {b0.x,b0.y,b0.z,b0.w,b1.x,b1.y,b1.z,b1.w};
#pragma unroll
            for (int i = 0; i < 8; i++)
#pragma unroll
                for (int j = 0; j < 8; j++)
                    acc[i][j] += ar[i] * br[j];
        }
        if (nxt < DD) {
            int nb = buf ^ 1;
            As[nb][kqA+0][rA] = av.x; As[nb][kqA+1][rA] = av.y;
            As[nb][kqA+2][rA] = av.z; As[nb][kqA+3][rA] = av.w;
            *(float4*)&Bs[nb][kB][nB] = bv;
            __syncthreads();
            buf = nb;
        }
    }

    if (MODE == 0) {
#pragma unroll
        for (int i = 0; i < 8; i++) {
            int m = m0 + ty * 8 + i;
            if (m < cnt) {
                float* hr = &g_h[(size_t)(base + m) * HH + n0 + tx * 8];
                float4 v0, v1;
                v0.x = gelu_tanh(acc[i][0]); v0.y = gelu_tanh(acc[i][1]);
                v0.z = gelu_tanh(acc[i][2]); v0.w = gelu_tanh(acc[i][3]);
                v1.x = gelu_tanh(acc[i][4]); v1.y = gelu_tanh(acc[i][5]);
                v1.z = gelu_tanh(acc[i][6]); v1.w = gelu_tanh(acc[i][7]);
                *(float4*)(hr)     = v0;
                *(float4*)(hr + 4) = v1;
            }
        }
    } else {
#pragma unroll
        for (int i = 0; i < 8; i++) {
            int m = m0 + ty * 8 + i;
            if (m < cnt) {
                int slot = base + m;
                int tok = g_slot_tok[slot];
                float gt = g_slot_gate[slot];
                float* yr = y + (size_t)tok * DD + n0 + tx * 8;
#pragma unroll
                for (int j = 0; j < 8; j++)
                    atomicAdd(&yr[j], gt * acc[i][j]);
            }
        }
    }
}

// ---------------- 6) aux loss ----------------
__global__ void loss_kernel(float* __restrict__ out, int out_size) {
    if (threadIdx.x != 0 || blockIdx.x != 0) return;
    float gs[EE], ps[EE], cs[EE];
    float sg = 0.f, sp = 0.f, sc = 0.f;
#pragma unroll
    for (int e = 0; e < EE; e++) {
        gs[e] = g_gates_sum[e]; sg += fabsf(gs[e]);
        ps[e] = g_probs_sum[e]; sp += fabsf(ps[e]);
        cs[e] = (float)g_count[e]; sc += fabsf(cs[e]);
    }
    sg = fmaxf(sg, 1e-12f); sp = fmaxf(sp, 1e-12f); sc = fmaxf(sc, 1e-12f);
    // cv_squared(l1norm(gates_sum)), unbiased variance
    float m = 0.f;
#pragma unroll
    for (int e = 0; e < EE; e++) { gs[e] /= sg; m += gs[e]; }
    m /= EE;
    float var = 0.f;
#pragma unroll
    for (int e = 0; e < EE; e++) { float d = gs[e] - m; var += d * d; }
    var /= (EE - 1);
    float cv = var / (m * m + 1e-10f);
    // switch loss
    float sw = 0.f;
#pragma unroll
    for (int e = 0; e < EE; e++) sw += (ps[e] / sp) * (cs[e] / sc);
    sw *= EE;
    // z loss
    float zl = g_z / (float)TT;
    float loss = 0.01f * cv + 0.01f * sw + 0.001f * zl;
    if (out_size > TT * DD) out[TT * DD] = loss;
}

// ---------------- host ----------------
extern "C" void kernel_launch(void* const* d_in, const int* in_sizes, int n_in,
                              void* d_out, int out_size) {
    const float* x     = (const float*)d_in[0];
    const float* wg    = (const float*)d_in[1];
    const float* w_in  = (const float*)d_in[2];
    const float* w_out = (const float*)d_in[3];
    float* y = (float*)d_out;

    cudaMemsetAsync(d_out, 0, (size_t)out_size * sizeof(float), 0);
    init_kernel<<<1, 32>>>();
    gate_kernel<<<TT, 128>>>(x, wg);
    reduce_kernel<<<TT / 256, 256>>>();
    prefix_kernel<<<1, 32>>>();
    scatter_kernel<<<TT / 256, 256>>>();
    gemm_kernel<0><<<dim3(64, HH / 128, EE), 256>>>(x, w_in, nullptr);
    gemm_kernel<1><<<dim3(64, DD / 128, EE), 256>>>(nullptr, w_out, y);
    loss_kernel<<<1, 32>>>(y, out_size);
}

// round 15
// speedup vs baseline: 1.0456x; 1.0456x over previous
#include <cuda_runtime.h>
#include <math.h>
#include <stdint.h>

// Problem constants (fixed by the reference)
#define TT 8192          // tokens = B*L
#define DD 1024          // input dim
#define HH 1024          // expert hidden
#define EE 8             // experts
#define KSEL 2           // top-k
#define SLOTS (TT*KSEL)  // 16384 token-expert pairs

// ---------------- device scratch (no allocations allowed) ----------------
__device__ int   g_top_idx[SLOTS];
__device__ float g_top_gate[SLOTS];
__device__ float g_probs[TT*EE];
__device__ float g_lse2[TT];
__device__ float g_probs_sum[EE];
__device__ float g_gates_sum[EE];
__device__ int   g_count[EE];
__device__ int   g_off[EE+1];
__device__ int   g_cur[EE];
__device__ int   g_slot_tok[SLOTS];
__device__ float g_slot_gate[SLOTS];
__device__ float g_h[(size_t)SLOTS * HH];   // 64 MB intermediate (GELU(x@w_in))
__device__ float g_z;                        // sum of lse^2

// ---------------- packed f32x2 helpers (FMA pipe, NOT tensor) ----------------
#define PACK2(dst, s) asm("mov.b64 %0, {%1, %1};" : "=l"(dst) : "f"(s))
#define UNPK(lo, hi, p) asm("mov.b64 {%0, %1}, %2;" : "=f"(lo), "=f"(hi) : "l"(p))
#define FMA2(c, a, b) asm("fma.rn.f32x2 %0, %1, %2, %0;" : "+l"(c) : "l"(a), "l"(b))

// one A-broadcast times 4 B-pairs into one accumulator row
#define ROWF(i) do { \
    FMA2(c##i##0, ap, bp0); \
    FMA2(c##i##1, ap, bp1); \
    FMA2(c##i##2, ap, bp2); \
    FMA2(c##i##3, ap, bp3); \
} while (0)

// ---------------- helpers ----------------
__device__ __forceinline__ float gelu_tanh(float v) {
    // jax.nn.gelu default (approximate=True)
    const float c0 = 0.7978845608028654f;    // sqrt(2/pi)
    return 0.5f * v * (1.0f + tanhf(c0 * (v + 0.044715f * v * v * v)));
}

// ---------------- 0) reset accumulators (graph-replay safe) ----------------
__global__ void init_kernel() {
    int i = threadIdx.x;
    if (i < EE) { g_probs_sum[i] = 0.f; g_gates_sum[i] = 0.f; g_count[i] = 0; g_cur[i] = 0; }
    if (i == 0) g_z = 0.f;
}

// ---------------- 1) gating: logits, softmax, top-2, lse^2 ----------------
__global__ void __launch_bounds__(128) gate_kernel(const float* __restrict__ x,
                                                   const float* __restrict__ wg) {
    int t = blockIdx.x;
    int tid = threadIdx.x;   // 128 threads
    const float* xr = x + (size_t)t * DD;
    float part[EE];
#pragma unroll
    for (int e = 0; e < EE; e++) part[e] = 0.f;

    for (int i = tid; i < DD; i += 128) {
        float xv = xr[i];
        const float4* w4 = (const float4*)(wg + (size_t)i * EE);
        float4 w0 = w4[0], w1 = w4[1];
        part[0] += xv * w0.x; part[1] += xv * w0.y;
        part[2] += xv * w0.z; part[3] += xv * w0.w;
        part[4] += xv * w1.x; part[5] += xv * w1.y;
        part[6] += xv * w1.z; part[7] += xv * w1.w;
    }
#pragma unroll
    for (int e = 0; e < EE; e++)
#pragma unroll
        for (int o = 16; o > 0; o >>= 1)
            part[e] += __shfl_down_sync(0xffffffffu, part[e], o);

    __shared__ float sred[4][EE];
    int wid = tid >> 5, lid = tid & 31;
    if (lid == 0)
#pragma unroll
        for (int e = 0; e < EE; e++) sred[wid][e] = part[e];
    __syncthreads();

    if (tid == 0) {
        float logit[EE];
#pragma unroll
        for (int e = 0; e < EE; e++)
            logit[e] = sred[0][e] + sred[1][e] + sred[2][e] + sred[3][e];
        float mx = logit[0];
#pragma unroll
        for (int e = 1; e < EE; e++) mx = fmaxf(mx, logit[e]);
        float p[EE]; float se = 0.f;
#pragma unroll
        for (int e = 0; e < EE; e++) { p[e] = expf(logit[e] - mx); se += p[e]; }
        float inv = 1.f / se;
#pragma unroll
        for (int e = 0; e < EE; e++) { p[e] *= inv; g_probs[(size_t)t * EE + e] = p[e]; }
        float lse = mx + logf(se);
        g_lse2[t] = lse * lse;

        // top-2 (jax top_k: largest first, lowest index on tie)
        int i0 = 0;
#pragma unroll
        for (int e = 1; e < EE; e++) if (p[e] > p[i0]) i0 = e;
        int i1 = -1;
#pragma unroll
        for (int e = 0; e < EE; e++) {
            if (e == i0) continue;
            if (i1 < 0 || p[e] > p[i1]) i1 = e;
        }
        g_top_idx[t*2+0] = i0; g_top_gate[t*2+0] = p[i0];
        g_top_idx[t*2+1] = i1; g_top_gate[t*2+1] = p[i1];
    }
}

// ---------------- 2) reduce per-expert stats ----------------
__global__ void __launch_bounds__(256) reduce_kernel() {
    __shared__ float sp[EE]; __shared__ float sg[EE]; __shared__ int sc[EE]; __shared__ float sz;
    int tid = threadIdx.x;
    if (tid < EE) { sp[tid] = 0.f; sg[tid] = 0.f; sc[tid] = 0; }
    if (tid == 0) sz = 0.f;
    __syncthreads();

    int t = blockIdx.x * blockDim.x + tid;
    float p[EE]; float z = 0.f;
    if (t < TT) {
#pragma unroll
        for (int e = 0; e < EE; e++) p[e] = g_probs[(size_t)t * EE + e];
        z = g_lse2[t];
    } else {
#pragma unroll
        for (int e = 0; e < EE; e++) p[e] = 0.f;
    }
#pragma unroll
    for (int e = 0; e < EE; e++)
#pragma unroll
        for (int o = 16; o > 0; o >>= 1)
            p[e] += __shfl_down_sync(0xffffffffu, p[e], o);
#pragma unroll
    for (int o = 16; o > 0; o >>= 1) z += __shfl_down_sync(0xffffffffu, z, o);

    if ((tid & 31) == 0) {
#pragma unroll
        for (int e = 0; e < EE; e++) atomicAdd(&sp[e], p[e]);
        atomicAdd(&sz, z);
    }
    if (t < TT) {
#pragma unroll
        for (int k = 0; k < KSEL; k++) {
            int e = g_top_idx[t*2+k];
            atomicAdd(&sg[e], g_top_gate[t*2+k]);
            atomicAdd(&sc[e], 1);
        }
    }
    __syncthreads();
    if (tid < EE) {
        atomicAdd(&g_probs_sum[tid], sp[tid]);
        atomicAdd(&g_gates_sum[tid], sg[tid]);
        atomicAdd(&g_count[tid], sc[tid]);
    }
    if (tid == 0) atomicAdd(&g_z, sz);
}

// ---------------- 3) prefix + scatter ----------------
__global__ void prefix_kernel() {
    if (threadIdx.x == 0) {
        int s = 0;
#pragma unroll
        for (int e = 0; e < EE; e++) { g_off[e] = s; s += g_count[e]; }
        g_off[EE] = s;
    }
}

__global__ void __launch_bounds__(256) scatter_kernel() {
    int t = blockIdx.x * blockDim.x + threadIdx.x;
    if (t >= TT) return;
#pragma unroll
    for (int k = 0; k < KSEL; k++) {
        int e = g_top_idx[t*2+k];
        int pos = g_off[e] + atomicAdd(&g_cur[e], 1);
        g_slot_tok[pos] = t;
        g_slot_gate[pos] = g_top_gate[t*2+k];
    }
}

// ---------------- 4/5) grouped GEMM (f32x2 packed SGEMM) ----------------
// MODE 0: h = gelu(x[tok] @ w_in[e])           -> g_h
// MODE 1: y[tok] += gate * (g_h @ w_out[e])    (atomicAdd combine)
// Tile: 128(M) x 128(N) x 8(K), 256 threads, 8x8 per thread, double-buffered SMEM.
// Inner product uses fma.rn.f32x2 (2 FMA/lane/instr): 32 FFMA2 + 8 packs per kk
// replaces 64 FFMA -> ~2x fp32 throughput on the Blackwell packed FMA pipe.
template<int MODE>
__global__ void __launch_bounds__(256) gemm_kernel(const float* __restrict__ x,
                                                   const float* __restrict__ B_all,
                                                   float* __restrict__ y) {
    int e = blockIdx.z;
    int cnt = g_count[e];
    int m0 = blockIdx.x * 128;
    if (m0 >= cnt) return;
    int n0 = blockIdx.y * 128;
    int base = g_off[e];
    const float* B = B_all + (size_t)e * DD * HH;

    __shared__ float As[2][8][128];
    __shared__ float Bs[2][8][128];

    int tid = threadIdx.x;
    int tx = tid & 15, ty = tid >> 4;      // 16x16 thread grid, 8x8 microtile

    // 32 named packed accumulators: rows 0..7 (m), pairs 0..3 (n)
    unsigned long long c00=0, c01=0, c02=0, c03=0;
    unsigned long long c10=0, c11=0, c12=0, c13=0;
    unsigned long long c20=0, c21=0, c22=0, c23=0;
    unsigned long long c30=0, c31=0, c32=0, c33=0;
    unsigned long long c40=0, c41=0, c42=0, c43=0;
    unsigned long long c50=0, c51=0, c52=0, c53=0;
    unsigned long long c60=0, c61=0, c62=0, c63=0;
    unsigned long long c70=0, c71=0, c72=0, c73=0;

    // A-load: 256 float4 per K-tile (128 rows x 8 k), one per thread
    int rA  = tid >> 1;            // row 0..127
    int kqA = (tid & 1) * 4;       // k offset 0 or 4
    int mA = m0 + rA;
    bool vA = (mA < cnt);
    int slotA = vA ? (base + mA) : base;
    const float* aptr;
    if (MODE == 0) {
        int tok = vA ? g_slot_tok[slotA] : 0;
        aptr = x + (size_t)tok * DD + kqA;
    } else {
        aptr = g_h + (size_t)slotA * HH + kqA;
    }
    // B-load: 256 float4 per K-tile (8 k x 128 n), one per thread
    int kB = tid >> 5;             // 0..7
    int nB = (tid & 31) * 4;       // float4 col offset
    const float* bptr = B + (size_t)kB * 1024 + n0 + nB;

    // prologue: load tile 0
    float4 av = vA ? *(const float4*)(aptr) : make_float4(0.f,0.f,0.f,0.f);
    float4 bv = *(const float4*)(bptr);

    int buf = 0;
    As[0][kqA+0][rA] = av.x; As[0][kqA+1][rA] = av.y;
    As[0][kqA+2][rA] = av.z; As[0][kqA+3][rA] = av.w;
    *(float4*)&Bs[0][kB][nB] = bv;
    __syncthreads();

    for (int k0 = 0; k0 < DD; k0 += 8) {
        int nxt = k0 + 8;
        if (nxt < DD) {
            av = vA ? *(const float4*)(aptr + nxt) : make_float4(0.f,0.f,0.f,0.f);
            bv = *(const float4*)(bptr + (size_t)nxt * 1024);
        }
#pragma unroll
        for (int kk = 0; kk < 8; kk++) {
            float4 a0 = *(const float4*)&As[buf][kk][ty * 8];
            float4 a1 = *(const float4*)&As[buf][kk][ty * 8 + 4];
            const unsigned long long* bq = (const unsigned long long*)&Bs[buf][kk][tx * 8];
            unsigned long long bp0 = bq[0], bp1 = bq[1], bp2 = bq[2], bp3 = bq[3];
            unsigned long long ap;
            PACK2(ap, a0.x); ROWF(0);
            PACK2(ap, a0.y); ROWF(1);
            PACK2(ap, a0.z); ROWF(2);
            PACK2(ap, a0.w); ROWF(3);
            PACK2(ap, a1.x); ROWF(4);
            PACK2(ap, a1.y); ROWF(5);
            PACK2(ap, a1.z); ROWF(6);
            PACK2(ap, a1.w); ROWF(7);
        }
        if (nxt < DD) {
            int nb = buf ^ 1;
            As[nb][kqA+0][rA] = av.x; As[nb][kqA+1][rA] = av.y;
            As[nb][kqA+2][rA] = av.z; As[nb][kqA+3][rA] = av.w;
            *(float4*)&Bs[nb][kB][nB] = bv;
            __syncthreads();
            buf = nb;
        }
    }

    // ---- epilogue ----
#define EPI_ROW(i, mi) do { \
    int m_ = m0 + ty * 8 + (mi); \
    if (m_ < cnt) { \
        float f0,f1,f2,f3,f4,f5,f6,f7; \
        UNPK(f0, f1, c##i##0); UNPK(f2, f3, c##i##1); \
        UNPK(f4, f5, c##i##2); UNPK(f6, f7, c##i##3); \
        if (MODE == 0) { \
            float* hr = &g_h[(size_t)(base + m_) * HH + n0 + tx * 8]; \
            float4 v0, v1; \
            v0.x = gelu_tanh(f0); v0.y = gelu_tanh(f1); \
            v0.z = gelu_tanh(f2); v0.w = gelu_tanh(f3); \
            v1.x = gelu_tanh(f4); v1.y = gelu_tanh(f5); \
            v1.z = gelu_tanh(f6); v1.w = gelu_tanh(f7); \
            *(float4*)(hr)     = v0; \
            *(float4*)(hr + 4) = v1; \
        } else { \
            int slot_ = base + m_; \
            int tok_ = g_slot_tok[slot_]; \
            float gt_ = g_slot_gate[slot_]; \
            float* yr = y + (size_t)tok_ * DD + n0 + tx * 8; \
            atomicAdd(&yr[0], gt_ * f0); atomicAdd(&yr[1], gt_ * f1); \
            atomicAdd(&yr[2], gt_ * f2); atomicAdd(&yr[3], gt_ * f3); \
            atomicAdd(&yr[4], gt_ * f4); atomicAdd(&yr[5], gt_ * f5); \
            atomicAdd(&yr[6], gt_ * f6); atomicAdd(&yr[7], gt_ * f7); \
        } \
    } \
} while (0)

    EPI_ROW(0, 0); EPI_ROW(1, 1); EPI_ROW(2, 2); EPI_ROW(3, 3);
    EPI_ROW(4, 4); EPI_ROW(5, 5); EPI_ROW(6, 6); EPI_ROW(7, 7);
#undef EPI_ROW
}

// ---------------- 6) aux loss ----------------
__global__ void loss_kernel(float* __restrict__ out, int out_size) {
    if (threadIdx.x != 0 || blockIdx.x != 0) return;
    float gs[EE], ps[EE], cs[EE];
    float sg = 0.f, sp = 0.f, sc = 0.f;
#pragma unroll
    for (int e = 0; e < EE; e++) {
        gs[e] = g_gates_sum[e]; sg += fabsf(gs[e]);
        ps[e] = g_probs_sum[e]; sp += fabsf(ps[e]);
        cs[e] = (float)g_count[e]; sc += fabsf(cs[e]);
    }
    sg = fmaxf(sg, 1e-12f); sp = fmaxf(sp, 1e-12f); sc = fmaxf(sc, 1e-12f);
    // cv_squared(l1norm(gates_sum)), unbiased variance
    float m = 0.f;
#pragma unroll
    for (int e = 0; e < EE; e++) { gs[e] /= sg; m += gs[e]; }
    m /= EE;
    float var = 0.f;
#pragma unroll
    for (int e = 0; e < EE; e++) { float d = gs[e] - m; var += d * d; }
    var /= (EE - 1);
    float cv = var / (m * m + 1e-10f);
    // switch loss
    float sw = 0.f;
#pragma unroll
    for (int e = 0; e < EE; e++) sw += (ps[e] / sp) * (cs[e] / sc);
    sw *= EE;
    // z loss
    float zl = g_z / (float)TT;
    float loss = 0.01f * cv + 0.01f * sw + 0.001f * zl;
    if (out_size > TT * DD) out[TT * DD] = loss;
}

// ---------------- host ----------------
extern "C" void kernel_launch(void* const* d_in, const int* in_sizes, int n_in,
                              void* d_out, int out_size) {
    const float* x     = (const float*)d_in[0];
    const float* wg    = (const float*)d_in[1];
    const float* w_in  = (const float*)d_in[2];
    const float* w_out = (const float*)d_in[3];
    float* y = (float*)d_out;

    cudaMemsetAsync(d_out, 0, (size_t)out_size * sizeof(float), 0);
    init_kernel<<<1, 32>>>();
    gate_kernel<<<TT, 128>>>(x, wg);
    reduce_kernel<<<TT / 256, 256>>>();
    prefix_kernel<<<1, 32>>>();
    scatter_kernel<<<TT / 256, 256>>>();
    gemm_kernel<0><<<dim3(64, HH / 128, EE), 256>>>(x, w_in, nullptr);
    gemm_kernel<1><<<dim3(64, DD / 128, EE), 256>>>(nullptr, w_out, y);
    loss_kernel<<<1, 32>>>(y, out_size);
}